// round 6
// baseline (speedup 1.0000x reference)
#include <cuda_runtime.h>
#include <cuda_bf16.h>

// EEBasis: out[n, 0, s] = exp(-|zeta[s]| * sqrt(diffs[n, center_idxs[s], 3]))
// N = 262144 rows, 64 centers (float4: dx,dy,dz,r2), 256 shells (4/center).
//
// Float4-linear input index == float4-linear output index (shells are
// center-grouped). Both 268 MB streams are single-touch:
//  - __ldcs loads (evict-first), __stcs stores (streaming)
//  - 2 items per thread, BLOCK-LOCAL: CTA covers a contiguous 2*256-float4
//    window; item0 = window + tid, item1 = window + 256 + tid. Each load is
//    unit-stride across the warp (4 lines per LDG.128 — R5 showed intra-
//    thread-adjacent pairs double L1 wavefronts), loads front-batched
//    (MLP=2; R3 showed MLP=4 overflows the L1tex queue, R4 showed
//    persistent loops serialize the stream). CTA footprint is one
//    contiguous 8KB window per stream for L2/TLB locality.

__global__ void __launch_bounds__(256) eebasis_kernel(
    const float4* __restrict__ diffs,       // [N*64] float4
    const float4* __restrict__ zetas4,      // [64] float4 (256 zetas)
    const int*    __restrict__ center_idxs, // [256]
    float4*       __restrict__ out,         // [N*64] float4
    int total)                               // N*64
{
    int i0 = blockIdx.x * (2 * 256) + threadIdx.x;
    int i1 = i0 + 256;
    if (i1 >= total) {                 // never taken for this shape, keeps it safe
        if (i0 >= total) return;
        i1 = i0;
    }

    int g0 = i0 & 63, n0 = i0 >> 6;
    int g1 = i1 & 63, n1 = i1 >> 6;

    // gather table (1KB, L1-resident)
    int c0 = __ldg(&center_idxs[4 * g0]);
    int c1 = __ldg(&center_idxs[4 * g1]);

    // front-batched streaming loads (MLP = 2), each unit-stride across warp
    float4 d0 = __ldcs(&diffs[n0 * 64 + c0]);
    float4 d1 = __ldcs(&diffs[n1 * 64 + c1]);

    float4 z0 = __ldg(&zetas4[g0]);   // 1KB table, L1-resident
    float4 z1 = __ldg(&zetas4[g1]);

    float r0 = sqrtf(d0.w);
    float r1 = sqrtf(d1.w);

    float4 o0, o1;
    o0.x = __expf(-fabsf(z0.x) * r0);
    o0.y = __expf(-fabsf(z0.y) * r0);
    o0.z = __expf(-fabsf(z0.z) * r0);
    o0.w = __expf(-fabsf(z0.w) * r0);

    o1.x = __expf(-fabsf(z1.x) * r1);
    o1.y = __expf(-fabsf(z1.y) * r1);
    o1.z = __expf(-fabsf(z1.z) * r1);
    o1.w = __expf(-fabsf(z1.w) * r1);

    __stcs(&out[i0], o0);
    __stcs(&out[i1], o1);
}

extern "C" void kernel_launch(void* const* d_in, const int* in_sizes, int n_in,
                              void* d_out, int out_size)
{
    const float* diffs       = (const float*)d_in[0];  // [N, 64, 4] f32
    const float* zetas       = (const float*)d_in[1];  // [256] f32
    const int*   center_idxs = (const int*)  d_in[2];  // [256] i32

    int n_rows = in_sizes[0] / (64 * 4);
    int total  = n_rows * 64;

    int threads = 256;
    int per_cta = 2 * threads;
    int blocks  = (total + per_cta - 1) / per_cta;

    eebasis_kernel<<<blocks, threads>>>(
        (const float4*)diffs,
        (const float4*)zetas,
        center_idxs,
        (float4*)d_out,
        total);
}

// round 7
// speedup vs baseline: 1.0195x; 1.0195x over previous
#include <cuda_runtime.h>
#include <cuda_bf16.h>

// EEBasis: out[n, 0, s] = exp(-|zeta[s]| * sqrt(diffs[n, center_idxs[s], 3]))
// N = 262144 rows, 64 centers (float4: dx,dy,dz,r2), 256 shells (4/center).
//
// Float4-linear input index == float4-linear output index (shells are
// center-grouped). Both 256 MiB streams are single-touch:
//  - __ldcs loads (evict-first), __stcs stores (streaming)
//  - 2 items per thread, split total/2 apart (both streams unit-stride
//    across the warp — R5 showed intra-thread-adjacent pairs double L1
//    wavefronts), loads front-batched (MLP=2; R3: MLP=4 overflows the
//    L1tex queue; R4: persistent loops serialize the request stream;
//    R6: block-local pairing is neutral-worse).
//  - 512-thread CTAs: 4 CTAs/SM keeps oe*MLP_p1 = 8 under the queue
//    threshold, halves CTA-dispatch count; warps/SM unchanged.

__global__ void __launch_bounds__(512) eebasis_kernel(
    const float4* __restrict__ diffs,       // [N*64] float4
    const float4* __restrict__ zetas4,      // [64] float4 (256 zetas)
    const int*    __restrict__ center_idxs, // [256]
    float4*       __restrict__ out,         // [N*64] float4
    int half)                                // total/2
{
    int i0 = blockIdx.x * blockDim.x + threadIdx.x;
    if (i0 >= half) return;
    int i1 = i0 + half;

    int g0 = i0 & 63, n0 = i0 >> 6;
    int g1 = i1 & 63, n1 = i1 >> 6;

    // gather table (1KB, L1-resident)
    int c0 = __ldg(&center_idxs[4 * g0]);
    int c1 = __ldg(&center_idxs[4 * g1]);

    // front-batched streaming loads (MLP = 2), each unit-stride across warp
    float4 d0 = __ldcs(&diffs[n0 * 64 + c0]);
    float4 d1 = __ldcs(&diffs[n1 * 64 + c1]);

    float4 z0 = __ldg(&zetas4[g0]);   // 1KB table, L1-resident
    float4 z1 = __ldg(&zetas4[g1]);

    float r0 = sqrtf(d0.w);
    float r1 = sqrtf(d1.w);

    float4 o0, o1;
    o0.x = __expf(-fabsf(z0.x) * r0);
    o0.y = __expf(-fabsf(z0.y) * r0);
    o0.z = __expf(-fabsf(z0.z) * r0);
    o0.w = __expf(-fabsf(z0.w) * r0);

    o1.x = __expf(-fabsf(z1.x) * r1);
    o1.y = __expf(-fabsf(z1.y) * r1);
    o1.z = __expf(-fabsf(z1.z) * r1);
    o1.w = __expf(-fabsf(z1.w) * r1);

    __stcs(&out[i0], o0);
    __stcs(&out[i1], o1);
}

extern "C" void kernel_launch(void* const* d_in, const int* in_sizes, int n_in,
                              void* d_out, int out_size)
{
    const float* diffs       = (const float*)d_in[0];  // [N, 64, 4] f32
    const float* zetas       = (const float*)d_in[1];  // [256] f32
    const int*   center_idxs = (const int*)  d_in[2];  // [256] i32

    int n_rows = in_sizes[0] / (64 * 4);
    int total  = n_rows * 64;
    int half   = total / 2;   // N is a power of two; total even

    int threads = 512;
    int blocks  = (half + threads - 1) / threads;

    eebasis_kernel<<<blocks, threads>>>(
        (const float4*)diffs,
        (const float4*)zetas,
        center_idxs,
        (float4*)d_out,
        half);
}